// round 6
// baseline (speedup 1.0000x reference)
#include <cuda_runtime.h>
#include <float.h>
#include <math.h>

#define BB   8
#define NN   4096
#define SS   1024
#define NSMP 32
#define CIN  64
#define CMLP 128
#define COUT 256

// ---------------- scratch (device globals; no runtime allocation) ----------
__device__ int   g_fps [BB*SS];
__device__ int   g_gidx[BB*SS*NSMP];
__device__ int   g_cnt [BB*NN];
__device__ float g_W   [CIN*COUT];
__device__ float g_bvec[COUT];
__device__ float g_h   [BB*NN*COUT];          // 33.5 MB, fits L2
__device__ float g_part[64*COUT*2];
__device__ float g_mean[COUT];
__device__ float g_istd[COUT];

// ---------------- packed f32x2 helpers (per-lane .rn => bit-exact) ---------
typedef unsigned long long u64;
__device__ __forceinline__ u64 f2pack(float a, float b) {
    u64 r; asm("mov.b64 %0, {%1, %2};" : "=l"(r) : "f"(a), "f"(b)); return r;
}
__device__ __forceinline__ void f2unpack(u64 v, float& a, float& b) {
    asm("mov.b64 {%0, %1}, %2;" : "=f"(a), "=f"(b) : "l"(v));
}
__device__ __forceinline__ u64 padd(u64 a, u64 b) {
    u64 r; asm("add.rn.f32x2 %0, %1, %2;" : "=l"(r) : "l"(a), "l"(b)); return r;
}
__device__ __forceinline__ u64 pmul(u64 a, u64 b) {
    u64 r; asm("mul.rn.f32x2 %0, %1, %2;" : "=l"(r) : "l"(a), "l"(b)); return r;
}

// exact (non-FMA) squared distance, matching XLA ((dx^2+dy^2)+dz^2)
__device__ __forceinline__ float dist3(float x, float y, float z,
                                       float cx, float cy, float cz) {
    float dx = __fsub_rn(x, cx);
    float dy = __fsub_rn(y, cy);
    float dz = __fsub_rn(z, cz);
    return __fadd_rn(__fadd_rn(__fmul_rn(dx, dx), __fmul_rn(dy, dy)),
                     __fmul_rn(dz, dz));
}

// ---------------- 1) farthest point sampling: one block per batch ----------
// 1024 threads, 4 points each (2 packed pairs). One __syncthreads per iter.
__global__ __launch_bounds__(1024, 1)
void fps_kernel(const float* __restrict__ xyz) {
    extern __shared__ float sm[];
    float* sx = sm;
    float* sy = sm + NN;
    float* sz = sm + 2 * NN;
    __shared__ unsigned svals[2][32];
    __shared__ int      sidx [2][32];

    const int b    = blockIdx.x;
    const int tid  = threadIdx.x;
    const int lane = tid & 31, wid = tid >> 5;

    const float* base = xyz + (size_t)b * NN * 3;
    for (int i = tid; i < NN; i += 1024) {
        sx[i] = base[3 * i + 0];
        sy[i] = base[3 * i + 1];
        sz[i] = base[3 * i + 2];
    }
    __syncthreads();

    // 2 packed pairs per thread: points tid*4 + {0..3}
    u64 px2[2], py2[2], pz2[2];
    float dmin[4];
#pragma unroll
    for (int j = 0; j < 2; ++j) {
        int p = tid * 4 + 2 * j;
        px2[j] = f2pack(sx[p], sx[p + 1]);
        py2[j] = f2pack(sy[p], sy[p + 1]);
        pz2[j] = f2pack(sz[p], sz[p + 1]);
        dmin[2 * j] = 1e10f; dmin[2 * j + 1] = 1e10f;
    }

    int far = 0;
    for (int it = 0; it < SS; ++it) {
        if (tid == 0) g_fps[b * SS + it] = far;
        const float cx = sx[far], cy = sy[far], cz = sz[far];
        const u64 ncx = f2pack(-cx, -cx);
        const u64 ncy = f2pack(-cy, -cy);
        const u64 ncz = f2pack(-cz, -cz);

        float bv = -1.0f;  // distances are >= 0
        int   bi = 0;
#pragma unroll
        for (int j = 0; j < 2; ++j) {
            u64 dx2 = padd(px2[j], ncx);   // x - cx  (exact: x + (-cx))
            u64 dy2 = padd(py2[j], ncy);
            u64 dz2 = padd(pz2[j], ncz);
            u64 s   = padd(padd(pmul(dx2, dx2), pmul(dy2, dy2)),
                           pmul(dz2, dz2));
            float d0, d1;
            f2unpack(s, d0, d1);
            float m0 = fminf(dmin[2 * j],     d0);
            float m1 = fminf(dmin[2 * j + 1], d1);
            dmin[2 * j]     = m0;
            dmin[2 * j + 1] = m1;
            if (m0 > bv) { bv = m0; bi = tid * 4 + 2 * j; }      // '>' keeps
            if (m1 > bv) { bv = m1; bi = tid * 4 + 2 * j + 1; }  // lowest idx
        }

        // warp argmax: lane order == index order, so lowest set lane wins ties
        unsigned vb   = __float_as_uint(bv);
        unsigned wmax = __reduce_max_sync(0xffffffffu, vb);
        unsigned msk  = __ballot_sync(0xffffffffu, vb == wmax);
        int      src  = __ffs(msk) - 1;
        int      wbi  = __shfl_sync(0xffffffffu, bi, src);

        const int buf = it & 1;
        if (lane == 0) { svals[buf][wid] = wmax; sidx[buf][wid] = wbi; }
        __syncthreads();

        // every warp redundantly reduces the 32 leader slots -> same 'far'
        unsigned v  = svals[buf][lane];
        int      fi = sidx [buf][lane];
        unsigned gm = __reduce_max_sync(0xffffffffu, v);
        unsigned m2 = __ballot_sync(0xffffffffu, v == gm);
        int      s2 = __ffs(m2) - 1;
        far = __shfl_sync(0xffffffffu, fi, s2);
    }
}

// ---------------- 2) fused weights W = W1@Wc, bvec = b1@Wc + bc; zero counts
__global__ __launch_bounds__(256)
void wfuse_kernel(const float* __restrict__ W1, const float* __restrict__ b1,
                  const float* __restrict__ Wc, const float* __restrict__ bc) {
    const int r = blockIdx.x;   // 0..63
    const int c = threadIdx.x;  // 0..255
    float acc = 0.f;
#pragma unroll 8
    for (int k = 0; k < CMLP; ++k)
        acc = fmaf(W1[r * CMLP + k], Wc[k * COUT + c], acc);
    g_W[r * COUT + c] = acc;
    if (r == 0) {
        float a = 0.f;
#pragma unroll 8
        for (int k = 0; k < CMLP; ++k)
            a = fmaf(b1[k], Wc[k * COUT + c], a);
        g_bvec[c] = a + bc[c];
    }
    // zero counts: 64 blocks x 512 entries
    g_cnt[r * 512 + c]       = 0;
    g_cnt[r * 512 + 256 + c] = 0;
}

// ---------------- 3) ball query: warp per centroid, shared SoA xyz --------
__global__ __launch_bounds__(256, 1)
void ballq_kernel(const float* __restrict__ xyz) {
    extern __shared__ float sm[];
    float* sx = sm;
    float* sy = sm + NN;
    float* sz = sm + 2 * NN;
    __shared__ int wbuf[8][NSMP];

    const int b = blockIdx.y;
    const int tid = threadIdx.x, lane = tid & 31, wid = tid >> 5;

    const float* base = xyz + (size_t)b * NN * 3;
    for (int i = tid; i < NN; i += 256) {
        sx[i] = base[3 * i + 0];
        sy[i] = base[3 * i + 1];
        sz[i] = base[3 * i + 2];
    }
    __syncthreads();

    const float R2 = (float)(0.15 * 0.15);  // match JAX f64->f32 cast

    for (int j = 0; j < 8; ++j) {
        const int s   = blockIdx.x * 64 + wid * 8 + j;
        const int far = g_fps[b * SS + s];
        const float cx = sx[far], cy = sy[far], cz = sz[far];

        int cnt = 0;
        for (int bp = 0; bp < NN; bp += 32) {
            int p = bp + lane;
            float d = dist3(sx[p], sy[p], sz[p], cx, cy, cz);
            bool in = (d <= R2);
            unsigned m = __ballot_sync(0xffffffffu, in);
            int off = __popc(m & ((1u << lane) - 1u));
            if (in && cnt + off < NSMP) wbuf[wid][cnt + off] = p;
            cnt += __popc(m);
            if (cnt >= NSMP) { cnt = NSMP; break; }
        }
        __syncwarp();
        int v = (lane < cnt) ? wbuf[wid][lane] : wbuf[wid][0];
        g_gidx[((size_t)b * SS + s) * NSMP + lane] = v;
        atomicAdd(&g_cnt[b * NN + v], 1);
        __syncwarp();
    }
}

// ---------------- 4) h = points @ W + bvec  (B*N x 64) @ (64 x 256) -------
__global__ __launch_bounds__(256, 2)
void hfull_kernel(const float* __restrict__ points) {
    __shared__ float psh[64 * CIN];  // 64 rows x 64 cols = 16 KB
    const int rowBase = blockIdx.x * 64;
    const int tid = threadIdx.x;

    {   // vectorized tile load
        const float4* src = (const float4*)(points + (size_t)rowBase * CIN);
        float4* dst = (float4*)psh;
        for (int i = tid; i < 64 * CIN / 4; i += 256) dst[i] = src[i];
    }
    __syncthreads();

    const int c = tid;  // channel
    float w[CIN];
#pragma unroll
    for (int k = 0; k < CIN; ++k) w[k] = g_W[k * COUT + c];
    const float bv = g_bvec[c];

    for (int r0 = 0; r0 < 64; r0 += 4) {
        float a0 = bv, a1 = bv, a2 = bv, a3 = bv;
        const float4* p0 = (const float4*)&psh[(r0 + 0) * CIN];
        const float4* p1 = (const float4*)&psh[(r0 + 1) * CIN];
        const float4* p2 = (const float4*)&psh[(r0 + 2) * CIN];
        const float4* p3 = (const float4*)&psh[(r0 + 3) * CIN];
#pragma unroll
        for (int k4 = 0; k4 < CIN / 4; ++k4) {
            float4 v0 = p0[k4], v1 = p1[k4], v2 = p2[k4], v3 = p3[k4];
            float w0 = w[4 * k4], w1 = w[4 * k4 + 1],
                  w2 = w[4 * k4 + 2], w3 = w[4 * k4 + 3];
            a0 = fmaf(v0.x, w0, a0); a0 = fmaf(v0.y, w1, a0);
            a0 = fmaf(v0.z, w2, a0); a0 = fmaf(v0.w, w3, a0);
            a1 = fmaf(v1.x, w0, a1); a1 = fmaf(v1.y, w1, a1);
            a1 = fmaf(v1.z, w2, a1); a1 = fmaf(v1.w, w3, a1);
            a2 = fmaf(v2.x, w0, a2); a2 = fmaf(v2.y, w1, a2);
            a2 = fmaf(v2.z, w2, a2); a2 = fmaf(v2.w, w3, a2);
            a3 = fmaf(v3.x, w0, a3); a3 = fmaf(v3.y, w1, a3);
            a3 = fmaf(v3.z, w2, a3); a3 = fmaf(v3.w, w3, a3);
        }
        g_h[(size_t)(rowBase + r0 + 0) * COUT + c] = a0;
        g_h[(size_t)(rowBase + r0 + 1) * COUT + c] = a1;
        g_h[(size_t)(rowBase + r0 + 2) * COUT + c] = a2;
        g_h[(size_t)(rowBase + r0 + 3) * COUT + c] = a3;
    }
}

// ---------------- 5) BN stats: count-weighted sum / sumsq per channel -----
__global__ __launch_bounds__(256)
void stats1_kernel() {
    const int c  = threadIdx.x;
    const int r0 = blockIdx.x * 512;
    float s = 0.f, q = 0.f;
    for (int r = r0; r < r0 + 512; ++r) {
        int w = g_cnt[r];
        if (w) {
            float v  = g_h[(size_t)r * COUT + c];
            float wv = (float)w * v;
            s += wv;
            q = fmaf(wv, v, q);
        }
    }
    g_part[((size_t)blockIdx.x * COUT + c) * 2 + 0] = s;
    g_part[((size_t)blockIdx.x * COUT + c) * 2 + 1] = q;
}

__global__ __launch_bounds__(256)
void stats2_kernel() {
    const int c = threadIdx.x;
    float s = 0.f, q = 0.f;
    for (int j = 0; j < 64; ++j) {
        s += g_part[((size_t)j * COUT + c) * 2 + 0];
        q += g_part[((size_t)j * COUT + c) * 2 + 1];
    }
    const float M = (float)(BB * SS * NSMP);  // 262144
    float mean = s / M;
    float var  = q / M - mean * mean;
    g_mean[c] = mean;
    g_istd[c] = 1.0f / sqrtf(var + 1e-5f);
}

// ---------------- 6) gather + max/min + BN-affine + relu ------------------
// max_n relu(a*h+b) == relu(a * (a>=0 ? max_n h : min_n h) + b)
__global__ __launch_bounds__(256)
void final_kernel(const float* __restrict__ gamma,
                  const float* __restrict__ beta,
                  float* __restrict__ out) {
    const int sgl = blockIdx.x;      // 0..8191
    const int b   = sgl >> 10;
    const int c   = threadIdx.x;

    __shared__ int idxs[NSMP];
    if (c < NSMP) idxs[c] = g_gidx[(size_t)sgl * NSMP + c];
    __syncthreads();

    const float* hb = g_h + (size_t)b * NN * COUT;
    float vmax = -FLT_MAX, vmin = FLT_MAX;
#pragma unroll
    for (int n = 0; n < NSMP; ++n) {
        float v = hb[(size_t)idxs[n] * COUT + c];
        vmax = fmaxf(vmax, v);
        vmin = fminf(vmin, v);
    }
    float a  = gamma[c] * g_istd[c];
    float bb = fmaf(-a, g_mean[c], beta[c]);
    float v  = (a >= 0.f) ? vmax : vmin;
    out[(size_t)sgl * COUT + c] = fmaxf(0.f, fmaf(a, v, bb));
}

// ---------------- launch ---------------------------------------------------
extern "C" void kernel_launch(void* const* d_in, const int* in_sizes, int n_in,
                              void* d_out, int out_size) {
    const float* xyz    = (const float*)d_in[0];
    // d_in[1] = t, unused by the reference
    const float* points = (const float*)d_in[2];
    const float* W1     = (const float*)d_in[3];
    const float* b1     = (const float*)d_in[4];
    const float* Wc     = (const float*)d_in[5];
    const float* bc     = (const float*)d_in[6];
    const float* gamma  = (const float*)d_in[7];
    const float* beta   = (const float*)d_in[8];
    float* out = (float*)d_out;

    const size_t smemXYZ = 3 * NN * sizeof(float);  // 49152 B dynamic

    // Opt in to >48KB total smem (dynamic 48KB + static arrays).
    cudaFuncSetAttribute(fps_kernel,
                         cudaFuncAttributeMaxDynamicSharedMemorySize, 65536);
    cudaFuncSetAttribute(ballq_kernel,
                         cudaFuncAttributeMaxDynamicSharedMemorySize, 65536);

    fps_kernel  <<<BB, 1024, smemXYZ>>>(xyz);
    wfuse_kernel<<<64, 256>>>(W1, b1, Wc, bc);
    ballq_kernel<<<dim3(16, BB), 256, smemXYZ>>>(xyz);
    hfull_kernel<<<(BB * NN) / 64, 256>>>(points);
    stats1_kernel<<<64, 256>>>();
    stats2_kernel<<<1, 256>>>();
    final_kernel<<<BB * SS, 256>>>(gamma, beta, out);
}

// round 7
// speedup vs baseline: 1.1565x; 1.1565x over previous
#include <cuda_runtime.h>
#include <float.h>
#include <math.h>

#define BB   8
#define NN   4096
#define SS   1024
#define NSMP 32
#define CIN  64
#define CMLP 128
#define COUT 256

// ---------------- scratch (device globals; no runtime allocation) ----------
__device__ int   g_fps [BB*SS];
__device__ int   g_gidx[BB*SS*NSMP];
__device__ int   g_cnt [BB*NN];
__device__ float g_W   [CIN*COUT];
__device__ float g_bvec[COUT];
__device__ float g_h   [BB*NN*COUT];          // 33.5 MB, fits L2
__device__ float g_part[256*COUT*2];
__device__ float g_mean[COUT];
__device__ float g_istd[COUT];

// ---------------- packed f32x2 helpers (per-lane .rn => bit-exact) ---------
typedef unsigned long long u64;
__device__ __forceinline__ u64 f2pack(float a, float b) {
    u64 r; asm("mov.b64 %0, {%1, %2};" : "=l"(r) : "f"(a), "f"(b)); return r;
}
__device__ __forceinline__ void f2unpack(u64 v, float& a, float& b) {
    asm("mov.b64 {%0, %1}, %2;" : "=f"(a), "=f"(b) : "l"(v));
}
__device__ __forceinline__ u64 padd(u64 a, u64 b) {
    u64 r; asm("add.rn.f32x2 %0, %1, %2;" : "=l"(r) : "l"(a), "l"(b)); return r;
}
__device__ __forceinline__ u64 pmul(u64 a, u64 b) {
    u64 r; asm("mul.rn.f32x2 %0, %1, %2;" : "=l"(r) : "l"(a), "l"(b)); return r;
}

// exact (non-FMA) squared distance, matching XLA ((dx^2+dy^2)+dz^2)
__device__ __forceinline__ float dist3(float x, float y, float z,
                                       float cx, float cy, float cz) {
    float dx = __fsub_rn(x, cx);
    float dy = __fsub_rn(y, cy);
    float dz = __fsub_rn(z, cz);
    return __fadd_rn(__fadd_rn(__fmul_rn(dx, dx), __fmul_rn(dy, dy)),
                     __fmul_rn(dz, dz));
}

// ---------------- 1) farthest point sampling: one block per batch ----------
// 256 threads, 16 points each (8 packed pairs). One __syncthreads per iter.
__global__ __launch_bounds__(256, 1)
void fps_kernel(const float* __restrict__ xyz) {
    extern __shared__ float sm[];
    float* sx = sm;
    float* sy = sm + NN;
    float* sz = sm + 2 * NN;
    __shared__ unsigned svals[2][8];
    __shared__ int      sidx [2][8];

    const int b    = blockIdx.x;
    const int tid  = threadIdx.x;
    const int lane = tid & 31, wid = tid >> 5;

    const float* base = xyz + (size_t)b * NN * 3;
    for (int i = tid; i < NN; i += 256) {
        sx[i] = base[3 * i + 0];
        sy[i] = base[3 * i + 1];
        sz[i] = base[3 * i + 2];
    }
    __syncthreads();

    // 8 packed pairs per thread: points tid*16 + {0..15}
    u64 px2[8], py2[8], pz2[8];
    float dmin[16];
#pragma unroll
    for (int j = 0; j < 8; ++j) {
        int p = tid * 16 + 2 * j;
        px2[j] = f2pack(sx[p], sx[p + 1]);
        py2[j] = f2pack(sy[p], sy[p + 1]);
        pz2[j] = f2pack(sz[p], sz[p + 1]);
        dmin[2 * j] = 1e10f; dmin[2 * j + 1] = 1e10f;
    }

    int far = 0;
    for (int it = 0; it < SS; ++it) {
        if (tid == 0) g_fps[b * SS + it] = far;
        const float cx = sx[far], cy = sy[far], cz = sz[far];
        const u64 ncx = f2pack(-cx, -cx);
        const u64 ncy = f2pack(-cy, -cy);
        const u64 ncz = f2pack(-cz, -cz);

#pragma unroll
        for (int j = 0; j < 8; ++j) {
            u64 dx2 = padd(px2[j], ncx);   // x - cx  (exact: x + (-cx))
            u64 dy2 = padd(py2[j], ncy);
            u64 dz2 = padd(pz2[j], ncz);
            u64 s   = padd(padd(pmul(dx2, dx2), pmul(dy2, dy2)),
                           pmul(dz2, dz2));
            float d0, d1;
            f2unpack(s, d0, d1);
            dmin[2 * j]     = fminf(dmin[2 * j],     d0);
            dmin[2 * j + 1] = fminf(dmin[2 * j + 1], d1);
        }

        // order-preserving argmax merge tree ('>=' keeps left = lowest index)
        float mv[8]; int mi[8];
#pragma unroll
        for (int k = 0; k < 8; ++k) {
            bool c = dmin[2 * k] >= dmin[2 * k + 1];
            mv[k] = c ? dmin[2 * k] : dmin[2 * k + 1];
            mi[k] = c ? 2 * k : 2 * k + 1;
        }
#pragma unroll
        for (int k = 0; k < 4; ++k) {
            bool c = mv[2 * k] >= mv[2 * k + 1];
            mv[k] = c ? mv[2 * k] : mv[2 * k + 1];
            mi[k] = c ? mi[2 * k] : mi[2 * k + 1];
        }
        {
            bool c0 = mv[0] >= mv[1];
            float a0 = c0 ? mv[0] : mv[1]; int b0 = c0 ? mi[0] : mi[1];
            bool c1 = mv[2] >= mv[3];
            float a1 = c1 ? mv[2] : mv[3]; int b1 = c1 ? mi[2] : mi[3];
            bool c  = a0 >= a1;
            mv[0] = c ? a0 : a1; mi[0] = c ? b0 : b1;
        }
        const float bv = mv[0];
        const int   bi = tid * 16 + mi[0];

        // warp argmax: lane order == index order, so lowest set lane wins ties
        unsigned vb   = __float_as_uint(bv);
        unsigned wmax = __reduce_max_sync(0xffffffffu, vb);
        unsigned msk  = __ballot_sync(0xffffffffu, vb == wmax);
        int      src  = __ffs(msk) - 1;
        int      wbi  = __shfl_sync(0xffffffffu, bi, src);

        const int buf = it & 1;
        if (lane == 0) { svals[buf][wid] = wmax; sidx[buf][wid] = wbi; }
        __syncthreads();

        // every warp redundantly reduces the 8 leader slots -> same 'far'
        unsigned v  = (lane < 8) ? svals[buf][lane] : 0u;
        int      fi = (lane < 8) ? sidx [buf][lane] : 0;
        unsigned gm = __reduce_max_sync(0xffffffffu, v);
        unsigned m2 = __ballot_sync(0xffffffffu, (v == gm) && (lane < 8));
        int      s2 = __ffs(m2) - 1;
        far = __shfl_sync(0xffffffffu, fi, s2);
    }
}

// ---------------- 2) fused weights W = W1@Wc, bvec = b1@Wc + bc; zero counts
__global__ __launch_bounds__(256)
void wfuse_kernel(const float* __restrict__ W1, const float* __restrict__ b1,
                  const float* __restrict__ Wc, const float* __restrict__ bc) {
    const int r = blockIdx.x;   // 0..63
    const int c = threadIdx.x;  // 0..255
    float acc = 0.f;
#pragma unroll 8
    for (int k = 0; k < CMLP; ++k)
        acc = fmaf(W1[r * CMLP + k], Wc[k * COUT + c], acc);
    g_W[r * COUT + c] = acc;
    if (r == 0) {
        float a = 0.f;
#pragma unroll 8
        for (int k = 0; k < CMLP; ++k)
            a = fmaf(b1[k], Wc[k * COUT + c], a);
        g_bvec[c] = a + bc[c];
    }
    // zero counts: 64 blocks x 512 entries
    g_cnt[r * 512 + c]       = 0;
    g_cnt[r * 512 + 256 + c] = 0;
}

// ---------------- 3) ball query: warp per centroid, shared SoA xyz --------
__global__ __launch_bounds__(256, 1)
void ballq_kernel(const float* __restrict__ xyz) {
    extern __shared__ float sm[];
    float* sx = sm;
    float* sy = sm + NN;
    float* sz = sm + 2 * NN;
    __shared__ int wbuf[8][NSMP];

    const int b = blockIdx.y;
    const int tid = threadIdx.x, lane = tid & 31, wid = tid >> 5;

    const float* base = xyz + (size_t)b * NN * 3;
    for (int i = tid; i < NN; i += 256) {
        sx[i] = base[3 * i + 0];
        sy[i] = base[3 * i + 1];
        sz[i] = base[3 * i + 2];
    }
    __syncthreads();

    const float R2 = (float)(0.15 * 0.15);  // match JAX f64->f32 cast

    for (int j = 0; j < 8; ++j) {
        const int s   = blockIdx.x * 64 + wid * 8 + j;
        const int far = g_fps[b * SS + s];
        const float cx = sx[far], cy = sy[far], cz = sz[far];

        int cnt = 0;
        for (int bp = 0; bp < NN; bp += 32) {
            int p = bp + lane;
            float d = dist3(sx[p], sy[p], sz[p], cx, cy, cz);
            bool in = (d <= R2);
            unsigned m = __ballot_sync(0xffffffffu, in);
            int off = __popc(m & ((1u << lane) - 1u));
            if (in && cnt + off < NSMP) wbuf[wid][cnt + off] = p;
            cnt += __popc(m);
            if (cnt >= NSMP) { cnt = NSMP; break; }
        }
        __syncwarp();
        int v = (lane < cnt) ? wbuf[wid][lane] : wbuf[wid][0];
        g_gidx[((size_t)b * SS + s) * NSMP + lane] = v;
        atomicAdd(&g_cnt[b * NN + v], 1);
        __syncwarp();
    }
}

// ---------------- 4) h = points @ W + bvec  (B*N x 64) @ (64 x 256) -------
__global__ __launch_bounds__(256, 2)
void hfull_kernel(const float* __restrict__ points) {
    __shared__ float psh[64 * CIN];  // 64 rows x 64 cols = 16 KB
    const int rowBase = blockIdx.x * 64;
    const int tid = threadIdx.x;

    {   // vectorized tile load
        const float4* src = (const float4*)(points + (size_t)rowBase * CIN);
        float4* dst = (float4*)psh;
        for (int i = tid; i < 64 * CIN / 4; i += 256) dst[i] = src[i];
    }
    __syncthreads();

    const int c = tid;  // channel
    float w[CIN];
#pragma unroll
    for (int k = 0; k < CIN; ++k) w[k] = g_W[k * COUT + c];
    const float bv = g_bvec[c];

    for (int r0 = 0; r0 < 64; r0 += 4) {
        float a0 = bv, a1 = bv, a2 = bv, a3 = bv;
        const float4* p0 = (const float4*)&psh[(r0 + 0) * CIN];
        const float4* p1 = (const float4*)&psh[(r0 + 1) * CIN];
        const float4* p2 = (const float4*)&psh[(r0 + 2) * CIN];
        const float4* p3 = (const float4*)&psh[(r0 + 3) * CIN];
#pragma unroll
        for (int k4 = 0; k4 < CIN / 4; ++k4) {
            float4 v0 = p0[k4], v1 = p1[k4], v2 = p2[k4], v3 = p3[k4];
            float w0 = w[4 * k4], w1 = w[4 * k4 + 1],
                  w2 = w[4 * k4 + 2], w3 = w[4 * k4 + 3];
            a0 = fmaf(v0.x, w0, a0); a0 = fmaf(v0.y, w1, a0);
            a0 = fmaf(v0.z, w2, a0); a0 = fmaf(v0.w, w3, a0);
            a1 = fmaf(v1.x, w0, a1); a1 = fmaf(v1.y, w1, a1);
            a1 = fmaf(v1.z, w2, a1); a1 = fmaf(v1.w, w3, a1);
            a2 = fmaf(v2.x, w0, a2); a2 = fmaf(v2.y, w1, a2);
            a2 = fmaf(v2.z, w2, a2); a2 = fmaf(v2.w, w3, a2);
            a3 = fmaf(v3.x, w0, a3); a3 = fmaf(v3.y, w1, a3);
            a3 = fmaf(v3.z, w2, a3); a3 = fmaf(v3.w, w3, a3);
        }
        g_h[(size_t)(rowBase + r0 + 0) * COUT + c] = a0;
        g_h[(size_t)(rowBase + r0 + 1) * COUT + c] = a1;
        g_h[(size_t)(rowBase + r0 + 2) * COUT + c] = a2;
        g_h[(size_t)(rowBase + r0 + 3) * COUT + c] = a3;
    }
}

// ---------------- 5) BN stats: count-weighted sum / sumsq per channel -----
__global__ __launch_bounds__(256)
void stats1_kernel() {
    const int c  = threadIdx.x;
    const int r0 = blockIdx.x * 128;
    float s = 0.f, q = 0.f;
    for (int r = r0; r < r0 + 128; ++r) {
        int w = g_cnt[r];
        if (w) {
            float v  = g_h[(size_t)r * COUT + c];
            float wv = (float)w * v;
            s += wv;
            q = fmaf(wv, v, q);
        }
    }
    g_part[((size_t)blockIdx.x * COUT + c) * 2 + 0] = s;
    g_part[((size_t)blockIdx.x * COUT + c) * 2 + 1] = q;
}

__global__ __launch_bounds__(256)
void stats2_kernel() {
    const int c = threadIdx.x;
    float s = 0.f, q = 0.f;
    for (int j = 0; j < 256; ++j) {
        s += g_part[((size_t)j * COUT + c) * 2 + 0];
        q += g_part[((size_t)j * COUT + c) * 2 + 1];
    }
    const float M = (float)(BB * SS * NSMP);  // 262144
    float mean = s / M;
    float var  = q / M - mean * mean;
    g_mean[c] = mean;
    g_istd[c] = 1.0f / sqrtf(var + 1e-5f);
}

// ---------------- 6) gather + max/min + BN-affine + relu ------------------
// max_n relu(a*h+b) == relu(a * (a>=0 ? max_n h : min_n h) + b)
__global__ __launch_bounds__(256)
void final_kernel(const float* __restrict__ gamma,
                  const float* __restrict__ beta,
                  float* __restrict__ out) {
    const int sgl = blockIdx.x;      // 0..8191
    const int b   = sgl >> 10;
    const int c   = threadIdx.x;

    __shared__ int idxs[NSMP];
    if (c < NSMP) idxs[c] = g_gidx[(size_t)sgl * NSMP + c];
    __syncthreads();

    const float* hb = g_h + (size_t)b * NN * COUT;
    float vmax = -FLT_MAX, vmin = FLT_MAX;
#pragma unroll
    for (int n = 0; n < NSMP; ++n) {
        float v = hb[(size_t)idxs[n] * COUT + c];
        vmax = fmaxf(vmax, v);
        vmin = fminf(vmin, v);
    }
    float a  = gamma[c] * g_istd[c];
    float bb = fmaf(-a, g_mean[c], beta[c]);
    float v  = (a >= 0.f) ? vmax : vmin;
    out[(size_t)sgl * COUT + c] = fmaxf(0.f, fmaf(a, v, bb));
}

// ---------------- launch ---------------------------------------------------
extern "C" void kernel_launch(void* const* d_in, const int* in_sizes, int n_in,
                              void* d_out, int out_size) {
    const float* xyz    = (const float*)d_in[0];
    // d_in[1] = t, unused by the reference
    const float* points = (const float*)d_in[2];
    const float* W1     = (const float*)d_in[3];
    const float* b1     = (const float*)d_in[4];
    const float* Wc     = (const float*)d_in[5];
    const float* bc     = (const float*)d_in[6];
    const float* gamma  = (const float*)d_in[7];
    const float* beta   = (const float*)d_in[8];
    float* out = (float*)d_out;

    const size_t smemXYZ = 3 * NN * sizeof(float);  // 49152 B dynamic

    // Opt in to >48KB total smem (dynamic 48KB + static arrays).
    cudaFuncSetAttribute(fps_kernel,
                         cudaFuncAttributeMaxDynamicSharedMemorySize, 65536);
    cudaFuncSetAttribute(ballq_kernel,
                         cudaFuncAttributeMaxDynamicSharedMemorySize, 65536);

    fps_kernel  <<<BB, 256, smemXYZ>>>(xyz);
    wfuse_kernel<<<64, 256>>>(W1, b1, Wc, bc);
    ballq_kernel<<<dim3(16, BB), 256, smemXYZ>>>(xyz);
    hfull_kernel<<<(BB * NN) / 64, 256>>>(points);
    stats1_kernel<<<256, 256>>>();
    stats2_kernel<<<1, 256>>>();
    final_kernel<<<BB * SS, 256>>>(gamma, beta, out);
}